// round 8
// baseline (speedup 1.0000x reference)
#include <cuda_runtime.h>
#include <math.h>

// ---------------------------------------------------------------------------
// Fused single kernel, 5633 blocks x 256 threads.
//   blocks 1..5632 : streaming GAP reduction (identical to proven R5 config)
//   block 0        : loads LN params, spins on g_count while keep-warming the
//                    weight matrices in L2, then runs the whole epilogue.
// Partial-sum layout (deterministic):
//   x2: 32/slice -> 4096 @ g_part[0]; x1: 4/slice -> 1024 @ g_part[4096];
//   x0: 1/slice  ->  512 @ g_part[5120]
// ---------------------------------------------------------------------------

#define NRED 5632

__device__ float g_part[NRED];
__device__ int   g_count = 0;

// LN over a 128-thread group (g=0: warps 0-3 batch0, g=1: warps 4-7 batch1),
// 4 elements per thread, single fused sum/sumsq reduction, no long chains.
__device__ __forceinline__ void ln256(float* v, int n, int u, int g,
                                      int wid, int lane,
                                      const float* w, const float* b,
                                      float* sbuf)
{
    float x[4]; float a = 0.f, q = 0.f;
    #pragma unroll
    for (int k = 0; k < 4; k++) {
        int e = u + 128 * k;
        x[k] = (e < n) ? v[e] : 0.f;
        a += x[k]; q += x[k] * x[k];
    }
    #pragma unroll
    for (int o = 16; o; o >>= 1) {
        a += __shfl_down_sync(0xffffffffu, a, o);
        q += __shfl_down_sync(0xffffffffu, q, o);
    }
    if (lane == 0) { sbuf[wid * 2] = a; sbuf[wid * 2 + 1] = q; }
    __syncthreads();
    int wb = g << 3;                       // group's 4 warps * 2 slots
    a = sbuf[wb]     + sbuf[wb + 2] + sbuf[wb + 4] + sbuf[wb + 6];
    q = sbuf[wb + 1] + sbuf[wb + 3] + sbuf[wb + 5] + sbuf[wb + 7];
    float inv_n = 1.f / (float)n;
    float mu  = a * inv_n;
    float var = fmaxf(q * inv_n - mu * mu, 0.f);
    float r   = rsqrtf(var + 1e-5f);
    #pragma unroll
    for (int k = 0; k < 4; k++) {
        int e = u + 128 * k;
        if (e < n) v[e] = (x[k] - mu) * r * w[e] + b[e];
    }
    __syncthreads();
}

__global__ __launch_bounds__(256, 6) void fused(
    const float* __restrict__ x0,
    const float* __restrict__ x1,
    const float* __restrict__ x2,
    const float* __restrict__ ln1w, const float* __restrict__ ln1b,
    const float* __restrict__ ln2w, const float* __restrict__ ln2b,
    const float* __restrict__ ln3w, const float* __restrict__ ln3b,
    const float* __restrict__ ln4w, const float* __restrict__ ln4b,
    const float* __restrict__ ln5w, const float* __restrict__ ln5b,
    const float* __restrict__ mlp_w1, const float* __restrict__ mlp_b1,
    const float* __restrict__ mlp_w2, const float* __restrict__ mlp_b2,
    const float* __restrict__ conv_w, const float* __restrict__ conv_b,
    float* __restrict__ out)
{
    __shared__ __align__(16) float sv[2][448];   // GAP/LN workspace, later h2
    __shared__ __align__(16) float h1s[2][64];
    __shared__ float red[128 * 33];              // deferred-reduce partials
    __shared__ float s_w[1280];                  // ln1@0 ln2@64 ln3@192 ln4@448 ln5@832
    __shared__ float s_b[1280];
    __shared__ float s_b1[64];
    __shared__ float s_b2[448];
    __shared__ float s_bc[64];
    __shared__ float sbuf[16];
    __shared__ int   done_flag;

    int tid = threadIdx.x;

    // =======================================================================
    // Reducer blocks (identical streaming config to the proven split kernel)
    // =======================================================================
    if (blockIdx.x > 0) {
        int bid = blockIdx.x - 1;
        const float4* src;
        int nvec;
        if (bid < 4096) {
            src  = reinterpret_cast<const float4*>(x2) + (size_t)bid * 16384;
            nvec = 16384;
        } else if (bid < 5120) {
            src  = reinterpret_cast<const float4*>(x1) + (size_t)(bid - 4096) * 16384;
            nvec = 16384;
        } else {
            src  = reinterpret_cast<const float4*>(x0) + (size_t)(bid - 5120) * 8192;
            nvec = 8192;
        }

        float s = 0.f;
        #pragma unroll 4
        for (int i = tid; i < nvec; i += 256) {
            float4 a = __ldcs(src + i);      // streaming: evict-first in L2
            s += (a.x + a.y) + (a.z + a.w);
        }

        #pragma unroll
        for (int o = 16; o; o >>= 1) s += __shfl_down_sync(0xffffffffu, s, o);
        if ((tid & 31) == 0) sbuf[tid >> 5] = s;
        __syncthreads();
        if (tid < 8) {
            s = sbuf[tid];
            #pragma unroll
            for (int o = 4; o; o >>= 1) s += __shfl_down_sync(0x000000ffu, s, o);
            if (tid == 0) {
                g_part[bid] = s;
                __threadfence();
                atomicAdd(&g_count, 1);
            }
        }
        return;
    }

    // =======================================================================
    // Block 0: param load -> spin + keep-warm -> epilogue
    // =======================================================================
    for (int i = tid; i < 64;  i += 256) { s_w[i] = ln1w[i]; s_b[i] = ln1b[i];
                                           s_b1[i] = mlp_b1[i]; s_bc[i] = conv_b[i]; }
    for (int i = tid; i < 128; i += 256) { s_w[64  + i] = ln2w[i]; s_b[64  + i] = ln2b[i]; }
    for (int i = tid; i < 256; i += 256) { s_w[192 + i] = ln3w[i]; s_b[192 + i] = ln3b[i]; }
    for (int i = tid; i < 384; i += 256) { s_w[448 + i] = ln4w[i]; s_b[448 + i] = ln4b[i]; }
    for (int i = tid; i < 448; i += 256) { s_w[832 + i] = ln5w[i]; s_b[832 + i] = ln5b[i];
                                           s_b2[i] = mlp_b2[i]; }
    if (tid == 0) done_flag = 0;
    __syncthreads();

    // --- Spin until all partials are published; keep weights hot in L2 ---
    {
        const char* w1c = (const char*)mlp_w1;
        const char* w2c = (const char*)mlp_w2;
        const char* wcc = (const char*)conv_w;
        while (true) {
            if (tid == 0) done_flag = *(volatile int*)&g_count;
            __syncthreads();
            int c = done_flag;
            if (c == NRED) break;
            for (int l = tid; l < 896; l += 256) {     // 896 lines per matrix
                asm volatile("prefetch.global.L2 [%0];" :: "l"(w1c + (size_t)l * 128));
                asm volatile("prefetch.global.L2 [%0];" :: "l"(w2c + (size_t)l * 128));
                asm volatile("prefetch.global.L2 [%0];" :: "l"(wcc + (size_t)l * 128));
            }
            __nanosleep(c > 5400 ? 200 : 2000);
            __syncthreads();
        }
    }
    __threadfence();
    if (tid == 0) g_count = 0;            // reset for next graph replay
    __syncthreads();

    // --- Assemble raw GAP means (deterministic partial ordering) ---
    for (int idx = tid; idx < 896; idx += 256) {
        int b = idx >= 448;
        int t = idx - b * 448;
        float val;
        if (t < 64) {
            int base = (b * 64 + t) * 32;
            float s = 0.f;
            #pragma unroll
            for (int k = 0; k < 32; k++) s += g_part[base + k];
            val = s * (1.f / 2097152.f);
        } else if (t < 192) {
            int base = 4096 + (b * 128 + (t - 64)) * 4;
            float s = 0.f;
            #pragma unroll
            for (int k = 0; k < 4; k++) s += g_part[base + k];
            val = s * (1.f / 262144.f);
        } else {
            val = g_part[5120 + b * 256 + (t - 192)] * (1.f / 32768.f);
        }
        sv[b][t] = val;
    }
    __syncthreads();

    int g    = tid >> 7;          // 0: batch 0 (warps 0-3), 1: batch 1 (4-7)
    int u    = tid & 127;
    int wid  = tid >> 5;
    int lane = tid & 31;
    float* svg = sv[g];

    // --- LayerNorm chain (both batches concurrently) ---
    ln256(svg,        64, u, g, wid, lane, s_w,       s_b,       sbuf);
    ln256(svg +  64, 128, u, g, wid, lane, s_w + 64,  s_b + 64,  sbuf);
    ln256(svg + 192, 256, u, g, wid, lane, s_w + 192, s_b + 192, sbuf);
    ln256(svg +  64, 384, u, g, wid, lane, s_w + 448, s_b + 448, sbuf);
    ln256(svg,       448, u, g, wid, lane, s_w + 832, s_b + 832, sbuf);

    // =======================================================================
    // Stage 1: h1 = relu(W1 . out448 + b1). Warp-task per output, lanes read
    // coalesced float2 of the row (L2-hot), deferred smem reduce (no shfl).
    // =======================================================================
    {
        const float2* w1_2 = reinterpret_cast<const float2*>(mlp_w1);
        for (int bb = 0; bb < 2; bb++) {
            const float2* xv2 = reinterpret_cast<const float2*>(sv[bb]);
            #pragma unroll
            for (int j = 0; j < 8; j++) {
                int o = wid * 8 + j;
                float p = 0.f;
                #pragma unroll
                for (int m = 0; m < 7; m++) {
                    float2 wv = w1_2[o * 224 + m * 32 + lane];
                    float2 xv = xv2[m * 32 + lane];
                    p = fmaf(wv.x, xv.x, fmaf(wv.y, xv.y, p));
                }
                red[o * 33 + lane] = p;
            }
            __syncthreads();
            if (tid < 64) {
                float s = s_b1[tid];
                #pragma unroll
                for (int l = 0; l < 32; l++) s += red[tid * 33 + l];
                h1s[bb][tid] = fmaxf(s, 0.f);
            }
            __syncthreads();
        }
    }

    // =======================================================================
    // Stage 2: h2 = relu(W2 . h1 + b2), 896 outputs in 7 rounds of 128
    // warp-tasks; one coalesced float2 load per task, deferred reduce.
    // h2 overwrites sv (stage-1 fully consumed sv).
    // =======================================================================
    {
        const float2* w2_2 = reinterpret_cast<const float2*>(mlp_w2);
        for (int r = 0; r < 7; r++) {
            #pragma unroll
            for (int j = 0; j < 16; j++) {
                int tau = r * 128 + wid * 16 + j;
                int bb  = tau >= 448;
                int jj  = tau - bb * 448;
                float2 wv = w2_2[jj * 32 + lane];
                const float2* hv2 = reinterpret_cast<const float2*>(h1s[bb]);
                float2 hv = hv2[lane];
                red[(wid * 16 + j) * 33 + lane] = fmaf(wv.x, hv.x, wv.y * hv.y);
            }
            __syncthreads();
            if (tid < 128) {
                int tau = r * 128 + tid;
                int bb  = tau >= 448;
                int jj  = tau - bb * 448;
                float s = s_b2[jj];
                #pragma unroll
                for (int l = 0; l < 32; l++) s += red[tid * 33 + l];
                sv[bb][jj] = fmaxf(s, 0.f);
            }
            __syncthreads();
        }
    }

    // =======================================================================
    // Stage 3: o = sigmoid(Wc . h2 + bc), same shape as stage 1.
    // =======================================================================
    {
        const float2* wc_2 = reinterpret_cast<const float2*>(conv_w);
        for (int bb = 0; bb < 2; bb++) {
            const float2* xv2 = reinterpret_cast<const float2*>(sv[bb]);
            #pragma unroll
            for (int j = 0; j < 8; j++) {
                int o = wid * 8 + j;
                float p = 0.f;
                #pragma unroll
                for (int m = 0; m < 7; m++) {
                    float2 wv = wc_2[o * 224 + m * 32 + lane];
                    float2 xv = xv2[m * 32 + lane];
                    p = fmaf(wv.x, xv.x, fmaf(wv.y, xv.y, p));
                }
                red[o * 33 + lane] = p;
            }
            __syncthreads();
            if (tid < 64) {
                float s = s_bc[tid];
                #pragma unroll
                for (int l = 0; l < 32; l++) s += red[tid * 33 + l];
                out[bb * 64 + tid] = 1.f / (1.f + expf(-s));
            }
            __syncthreads();
        }
    }
}

// ---------------------------------------------------------------------------

extern "C" void kernel_launch(void* const* d_in, const int* in_sizes, int n_in,
                              void* d_out, int out_size)
{
    fused<<<NRED + 1, 256>>>(
        (const float*)d_in[0], (const float*)d_in[1], (const float*)d_in[2],
        (const float*)d_in[3],  (const float*)d_in[4],   // ln1
        (const float*)d_in[5],  (const float*)d_in[6],   // ln2
        (const float*)d_in[7],  (const float*)d_in[8],   // ln3
        (const float*)d_in[9],  (const float*)d_in[10],  // ln4
        (const float*)d_in[11], (const float*)d_in[12],  // ln5
        (const float*)d_in[13], (const float*)d_in[14],  // mlp1
        (const float*)d_in[15], (const float*)d_in[16],  // mlp2
        (const float*)d_in[17], (const float*)d_in[18],  // conv
        (float*)d_out);
}

// round 9
// speedup vs baseline: 1.2148x; 1.2148x over previous
#include <cuda_runtime.h>
#include <math.h>

// ---------------------------------------------------------------------------
// Shapes
//   x0: [2, 256, 32^3]   -> 512 channel-slices of 32768 elems
//   x1: [2, 128, 64^3]   -> 256 channel-slices of 262144 elems
//   x2: [2,  64, 128^3]  -> 128 channel-slices of 2097152 elems
// Partial-sum layout (deterministic, no atomics):
//   x2: 32 partials/slice -> 4096 at g_part[0]
//   x1:  4 partials/slice -> 1024 at g_part[4096]
//   x0:  1 partial/slice  ->  512 at g_part[5120]
// ---------------------------------------------------------------------------

__device__ float g_part[5632];

__global__ __launch_bounds__(256) void gap_reduce(
    const float* __restrict__ x0,
    const float* __restrict__ x1,
    const float* __restrict__ x2)
{
    int bid = blockIdx.x;

    const float4* src;
    int nvec;
    if (bid < 4096) {
        src  = reinterpret_cast<const float4*>(x2) + (size_t)bid * 16384;
        nvec = 16384;
    } else if (bid < 5120) {
        src  = reinterpret_cast<const float4*>(x1) + (size_t)(bid - 4096) * 16384;
        nvec = 16384;
    } else {
        src  = reinterpret_cast<const float4*>(x0) + (size_t)(bid - 5120) * 8192;
        nvec = 8192;
    }

    float s = 0.f;
    #pragma unroll 4
    for (int i = threadIdx.x; i < nvec; i += 256) {
        float4 a = __ldcs(src + i);          // streaming: evict-first in L2
        s += (a.x + a.y) + (a.z + a.w);
    }

    __shared__ float sbuf[8];
    #pragma unroll
    for (int o = 16; o; o >>= 1) s += __shfl_down_sync(0xffffffffu, s, o);
    if ((threadIdx.x & 31) == 0) sbuf[threadIdx.x >> 5] = s;
    __syncthreads();
    if (threadIdx.x < 8) {
        s = sbuf[threadIdx.x];
        #pragma unroll
        for (int o = 4; o; o >>= 1) s += __shfl_down_sync(0x000000ffu, s, o);
        if (threadIdx.x == 0) g_part[bid] = s;
    }
}

// ---------------------------------------------------------------------------
// Epilogue: 1 block, 896 threads (warps 0-13 batch0, 14-27 batch1).
// At entry: fire-and-forget L2 prefetch of ALL weight lines (L2 is idle —
// the stream is done), then bulk-copy each matrix into dynamic smem
// (coalesced float4) right before its stage; stage-2/3 copies hit L2.
// Matmuls are thread-per-output FMA chains reading smem only.
// Smem row strides: 113 float4 (448-f rows), 17 float4 (64-f rows)
// -> stride mod 128B == 16B -> conflict-free LDS.128 phases.
// ---------------------------------------------------------------------------

extern __shared__ float4 dynw[];     // 7616 float4 = 121856 B

__device__ __forceinline__ float2 gsum2(float a, float b, float* sbuf)
{
    #pragma unroll
    for (int o = 16; o; o >>= 1) {
        a += __shfl_down_sync(0xffffffffu, a, o);
        b += __shfl_down_sync(0xffffffffu, b, o);
    }
    int w = threadIdx.x >> 5;
    int lane = threadIdx.x & 31;
    if (lane == 0) { sbuf[w] = a; sbuf[32 + w] = b; }
    __syncthreads();
    if (w == 0 || w == 14) {
        float x = (lane < 14) ? sbuf[w + lane]      : 0.f;
        float y = (lane < 14) ? sbuf[32 + w + lane] : 0.f;
        #pragma unroll
        for (int o = 16; o; o >>= 1) {
            x += __shfl_down_sync(0xffffffffu, x, o);
            y += __shfl_down_sync(0xffffffffu, y, o);
        }
        if (lane == 0) { sbuf[w] = x; sbuf[32 + w] = y; }
    }
    __syncthreads();
    int base = (threadIdx.x >= 448) ? 14 : 0;
    float2 r = make_float2(sbuf[base], sbuf[32 + base]);
    __syncthreads();
    return r;
}

__device__ __forceinline__ void ln_s(float* v, int n, int t,
                                     const float* w, const float* b,
                                     float* sbuf)
{
    float x  = (t < n) ? v[t] : 0.f;
    float2 s = gsum2(x, x * x, sbuf);
    float inv_n = 1.f / (float)n;
    float mu  = s.x * inv_n;
    float var = fmaxf(s.y * inv_n - mu * mu, 0.f);
    float r   = rsqrtf(var + 1e-5f);
    if (t < n) v[t] = (x - mu) * r * w[t] + b[t];
    __syncthreads();
}

__global__ __launch_bounds__(896) void epilogue(
    const float* __restrict__ ln1w, const float* __restrict__ ln1b,
    const float* __restrict__ ln2w, const float* __restrict__ ln2b,
    const float* __restrict__ ln3w, const float* __restrict__ ln3b,
    const float* __restrict__ ln4w, const float* __restrict__ ln4b,
    const float* __restrict__ ln5w, const float* __restrict__ ln5b,
    const float* __restrict__ mlp_w1, const float* __restrict__ mlp_b1,
    const float* __restrict__ mlp_w2, const float* __restrict__ mlp_b2,
    const float* __restrict__ conv_w, const float* __restrict__ conv_b,
    float* __restrict__ out)
{
    __shared__ __align__(16) float sv[2][448];   // LN workspace / h2
    __shared__ __align__(16) float h1s[2][64];
    __shared__ __align__(16) float red[2][448];
    __shared__ float sbuf[64];
    __shared__ float s_w[1280];   // ln1@0 ln2@64 ln3@192 ln4@448 ln5@832
    __shared__ float s_b[1280];
    __shared__ float s_b1[64];
    __shared__ float s_b2[448];
    __shared__ float s_bc[64];

    int tid = threadIdx.x;

    // --- 0: fire-and-forget L2 prefetch of all weight lines (2688 total) ---
    {
        const char* w1c = (const char*)mlp_w1;
        const char* w2c = (const char*)mlp_w2;
        const char* wcc = (const char*)conv_w;
        size_t off = (size_t)tid * 128;          // 896 threads x 1 line each
        asm volatile("prefetch.global.L2 [%0];" :: "l"(w1c + off));
        asm volatile("prefetch.global.L2 [%0];" :: "l"(w2c + off));
        asm volatile("prefetch.global.L2 [%0];" :: "l"(wcc + off));
    }

    // --- 1: stage-1 weight copy (latency hides under LN chain) ---
    {
        const float4* g4 = reinterpret_cast<const float4*>(mlp_w1);
        #pragma unroll
        for (int v = tid; v < 7168; v += 896) {
            int row = v / 112;           // 112 float4 per 448-float row
            int col = v - row * 112;
            dynw[row * 113 + col] = g4[v];
        }
    }

    // --- LN params + biases into smem ---
    if (tid < 64)   { s_w[tid]       = ln1w[tid]; s_b[tid]       = ln1b[tid]; }
    if (tid < 128)  { s_w[64 + tid]  = ln2w[tid]; s_b[64 + tid]  = ln2b[tid]; }
    if (tid < 256)  { s_w[192 + tid] = ln3w[tid]; s_b[192 + tid] = ln3b[tid]; }
    if (tid < 384)  { s_w[448 + tid] = ln4w[tid]; s_b[448 + tid] = ln4b[tid]; }
    if (tid < 448)  { s_w[832 + tid] = ln5w[tid]; s_b[832 + tid] = ln5b[tid]; }
    if (tid < 64)   s_b1[tid] = mlp_b1[tid];
    if (tid < 448)  s_b2[tid] = mlp_b2[tid];
    if (tid >= 448 && tid < 512) s_bc[tid - 448] = conv_b[tid - 448];

    int b = tid / 448;
    int t = tid - b * 448;
    float* svb = sv[b];

    // --- Assemble raw GAP means (deterministic partial ordering) ---
    if (t < 64) {
        int base = (b * 64 + t) * 32;
        float s = 0.f;
        #pragma unroll
        for (int k = 0; k < 32; k++) s += g_part[base + k];
        svb[t] = s * (1.f / 2097152.f);
    }
    if (t < 128) {
        int base = 4096 + (b * 128 + t) * 4;
        float s = 0.f;
        #pragma unroll
        for (int k = 0; k < 4; k++) s += g_part[base + k];
        svb[64 + t] = s * (1.f / 262144.f);
    }
    if (t < 256) {
        svb[192 + t] = g_part[5120 + b * 256 + t] * (1.f / 32768.f);
    }
    __syncthreads();

    // --- LayerNorm chain (w1 copy completes underneath) ---
    ln_s(svb,        64, t, s_w,       s_b,       sbuf);
    ln_s(svb +  64, 128, t, s_w + 64,  s_b + 64,  sbuf);
    ln_s(svb + 192, 256, t, s_w + 192, s_b + 192, sbuf);
    ln_s(svb +  64, 384, t, s_w + 448, s_b + 448, sbuf);
    ln_s(svb,       448, t, s_w + 832, s_b + 832, sbuf);
    // (last ln_s ends with __syncthreads -> w1 STS also drained)

    int c = t >> 6;                   // chunk 0..6
    int o = t & 63;                   // output 0..63

    // =======================================================================
    // Stage 1: partial dot over chunk c of row o, weights from smem.
    // =======================================================================
    {
        const float4* wr = dynw + o * 113 + c * 16;
        const float4* xr = reinterpret_cast<const float4*>(svb + c * 64);
        float p = 0.f;
        #pragma unroll
        for (int k = 0; k < 16; k++) {
            float4 wv = wr[k], xv = xr[k];
            p = fmaf(wv.x, xv.x, p); p = fmaf(wv.y, xv.y, p);
            p = fmaf(wv.z, xv.z, p); p = fmaf(wv.w, xv.w, p);
        }
        red[b][t] = p;
    }
    __syncthreads();
    if (tid < 128) {
        int bb = tid >> 6, oo = tid & 63;
        float acc = s_b1[oo];
        #pragma unroll
        for (int cc = 0; cc < 7; cc++) acc += red[bb][cc * 64 + oo];
        h1s[bb][oo] = fmaxf(acc, 0.f);
    }
    __syncthreads();

    // =======================================================================
    // Stage 2: copy w2 (448x64, L2-hot) into smem (17-f4 row stride), then
    // thread-per-(b,jj) dot of 64 from smem.
    // =======================================================================
    {
        const float4* g4 = reinterpret_cast<const float4*>(mlp_w2);
        #pragma unroll
        for (int v = tid; v < 7168; v += 896) {
            int row = v >> 4;            // 16 float4 per 64-float row
            int col = v & 15;
            dynw[row * 17 + col] = g4[v];
        }
    }
    __syncthreads();
    {
        const float4* wr = dynw + t * 17;            // row jj = t
        const float4* hr = reinterpret_cast<const float4*>(h1s[b]);
        float acc = s_b2[t];
        #pragma unroll
        for (int k = 0; k < 16; k++) {
            float4 wv = wr[k], hv = hr[k];
            acc = fmaf(wv.x, hv.x, acc); acc = fmaf(wv.y, hv.y, acc);
            acc = fmaf(wv.z, hv.z, acc); acc = fmaf(wv.w, hv.w, acc);
        }
        acc = fmaxf(acc, 0.f);
        __syncthreads();              // all stage-2 smem reads done
        svb[t] = acc;                 // h2 -> sv
    }
    __syncthreads();

    // =======================================================================
    // Stage 3: copy conv_w (L2-hot), chunk-dot, sigmoid finish.
    // =======================================================================
    {
        const float4* g4 = reinterpret_cast<const float4*>(conv_w);
        #pragma unroll
        for (int v = tid; v < 7168; v += 896) {
            int row = v / 112;
            int col = v - row * 112;
            dynw[row * 113 + col] = g4[v];
        }
    }
    __syncthreads();
    {
        const float4* wr = dynw + o * 113 + c * 16;
        const float4* xr = reinterpret_cast<const float4*>(svb + c * 64);
        float p = 0.f;
        #pragma unroll
        for (int k = 0; k < 16; k++) {
            float4 wv = wr[k], xv = xr[k];
            p = fmaf(wv.x, xv.x, p); p = fmaf(wv.y, xv.y, p);
            p = fmaf(wv.z, xv.z, p); p = fmaf(wv.w, xv.w, p);
        }
        red[b][t] = p;
    }
    __syncthreads();
    if (tid < 128) {
        int bb = tid >> 6, oo = tid & 63;
        float acc = s_bc[oo];
        #pragma unroll
        for (int cc = 0; cc < 7; cc++) acc += red[bb][cc * 64 + oo];
        out[bb * 64 + oo] = 1.f / (1.f + expf(-acc));
    }
}

// ---------------------------------------------------------------------------

extern "C" void kernel_launch(void* const* d_in, const int* in_sizes, int n_in,
                              void* d_out, int out_size)
{
    const float* x0 = (const float*)d_in[0];
    const float* x1 = (const float*)d_in[1];
    const float* x2 = (const float*)d_in[2];

    gap_reduce<<<5632, 256>>>(x0, x1, x2);

    const int dyn_bytes = 7616 * 16;   // 121856 B
    cudaFuncSetAttribute(epilogue,
                         cudaFuncAttributeMaxDynamicSharedMemorySize, dyn_bytes);

    epilogue<<<1, 896, dyn_bytes>>>(
        (const float*)d_in[3],  (const float*)d_in[4],
        (const float*)d_in[5],  (const float*)d_in[6],
        (const float*)d_in[7],  (const float*)d_in[8],
        (const float*)d_in[9],  (const float*)d_in[10],
        (const float*)d_in[11], (const float*)d_in[12],
        (const float*)d_in[13], (const float*)d_in[14],
        (const float*)d_in[15], (const float*)d_in[16],
        (const float*)d_in[17], (const float*)d_in[18],
        (float*)d_out);
}

// round 10
// speedup vs baseline: 1.2362x; 1.0176x over previous
#include <cuda_runtime.h>
#include <math.h>

// ---------------------------------------------------------------------------
// Shapes
//   x0: [2, 256, 32^3]   -> 512 channel-slices of 32768 elems
//   x1: [2, 128, 64^3]   -> 256 channel-slices of 262144 elems
//   x2: [2,  64, 128^3]  -> 128 channel-slices of 2097152 elems
// Partial-sum layout (deterministic, no atomics):
//   x2: 32 partials/slice -> 4096 at g_part[0]
//   x1:  4 partials/slice -> 1024 at g_part[4096]
//   x0:  1 partial/slice  ->  512 at g_part[5120]
// gap_reduce triggers programmatic launch completion at entry; the epilogue
// is launched with PSS so its weight staging overlaps the stream tail, and
// cudaGridDependencySynchronize() gates the g_part reads.
// ---------------------------------------------------------------------------

__device__ float g_part[5632];

__global__ __launch_bounds__(256) void gap_reduce(
    const float* __restrict__ x0,
    const float* __restrict__ x1,
    const float* __restrict__ x2)
{
#if __CUDA_ARCH__ >= 900
    cudaTriggerProgrammaticLaunchCompletion();
#endif
    int bid = blockIdx.x;

    const float4* src;
    int nvec;
    if (bid < 4096) {
        src  = reinterpret_cast<const float4*>(x2) + (size_t)bid * 16384;
        nvec = 16384;
    } else if (bid < 5120) {
        src  = reinterpret_cast<const float4*>(x1) + (size_t)(bid - 4096) * 16384;
        nvec = 16384;
    } else {
        src  = reinterpret_cast<const float4*>(x0) + (size_t)(bid - 5120) * 8192;
        nvec = 8192;
    }

    float s = 0.f;
    #pragma unroll 4
    for (int i = threadIdx.x; i < nvec; i += 256) {
        float4 a = __ldcs(src + i);          // streaming: evict-first in L2
        s += (a.x + a.y) + (a.z + a.w);
    }

    __shared__ float sbuf[8];
    #pragma unroll
    for (int o = 16; o; o >>= 1) s += __shfl_down_sync(0xffffffffu, s, o);
    if ((threadIdx.x & 31) == 0) sbuf[threadIdx.x >> 5] = s;
    __syncthreads();
    if (threadIdx.x < 8) {
        s = sbuf[threadIdx.x];
        #pragma unroll
        for (int o = 4; o; o >>= 1) s += __shfl_down_sync(0x000000ffu, s, o);
        if (threadIdx.x == 0) g_part[bid] = s;
    }
}

// ---------------------------------------------------------------------------
// Epilogue: 1 block, 896 threads (warps 0-13 batch0, 14-27 batch1).
// Pre-sync (overlapped with the stream tail via PDL): w1 -> smem, L2
// prefetch of w2/wc, LN params -> smem. Post-sync: g_part -> smem
// (coalesced), assembly (rotated banks), LN chain, 3 smem matmul stages.
// Smem row strides: 113 float4 (448-f rows), 17 float4 (64-f rows)
// -> stride mod 128B == 16B -> conflict-free LDS.128 phases.
// ---------------------------------------------------------------------------

extern __shared__ float4 dynw[];     // 7616 float4 = 121856 B

__device__ __forceinline__ float2 gsum2(float a, float b, float* sbuf)
{
    #pragma unroll
    for (int o = 16; o; o >>= 1) {
        a += __shfl_down_sync(0xffffffffu, a, o);
        b += __shfl_down_sync(0xffffffffu, b, o);
    }
    int w = threadIdx.x >> 5;
    int lane = threadIdx.x & 31;
    if (lane == 0) { sbuf[w] = a; sbuf[32 + w] = b; }
    __syncthreads();
    if (w == 0 || w == 14) {
        float x = (lane < 14) ? sbuf[w + lane]      : 0.f;
        float y = (lane < 14) ? sbuf[32 + w + lane] : 0.f;
        #pragma unroll
        for (int o = 16; o; o >>= 1) {
            x += __shfl_down_sync(0xffffffffu, x, o);
            y += __shfl_down_sync(0xffffffffu, y, o);
        }
        if (lane == 0) { sbuf[w] = x; sbuf[32 + w] = y; }
    }
    __syncthreads();
    int base = (threadIdx.x >= 448) ? 14 : 0;
    float2 r = make_float2(sbuf[base], sbuf[32 + base]);
    __syncthreads();
    return r;
}

__device__ __forceinline__ void ln_s(float* v, int n, int t,
                                     const float* w, const float* b,
                                     float* sbuf)
{
    float x  = (t < n) ? v[t] : 0.f;
    float2 s = gsum2(x, x * x, sbuf);
    float inv_n = 1.f / (float)n;
    float mu  = s.x * inv_n;
    float var = fmaxf(s.y * inv_n - mu * mu, 0.f);
    float r   = rsqrtf(var + 1e-5f);
    if (t < n) v[t] = (x - mu) * r * w[t] + b[t];
    __syncthreads();
}

__global__ __launch_bounds__(896) void epilogue(
    const float* __restrict__ ln1w, const float* __restrict__ ln1b,
    const float* __restrict__ ln2w, const float* __restrict__ ln2b,
    const float* __restrict__ ln3w, const float* __restrict__ ln3b,
    const float* __restrict__ ln4w, const float* __restrict__ ln4b,
    const float* __restrict__ ln5w, const float* __restrict__ ln5b,
    const float* __restrict__ mlp_w1, const float* __restrict__ mlp_b1,
    const float* __restrict__ mlp_w2, const float* __restrict__ mlp_b2,
    const float* __restrict__ conv_w, const float* __restrict__ conv_b,
    float* __restrict__ out)
{
    __shared__ __align__(16) float sv[2][448];   // LN workspace / h2
    __shared__ __align__(16) float h1s[2][64];
    __shared__ __align__(16) float red[2][448];
    __shared__ __align__(16) float s_g[5632];    // staged g_part
    __shared__ float sbuf[64];
    __shared__ float s_w[1280];   // ln1@0 ln2@64 ln3@192 ln4@448 ln5@832
    __shared__ float s_b[1280];
    __shared__ float s_b1[64];
    __shared__ float s_b2[448];
    __shared__ float s_bc[64];

    int tid = threadIdx.x;

    // ================= PRE-SYNC (overlaps the streaming tail) =============
    // L2 prefetch of w2 / wc (896 lines each, 1 per thread)
    {
        const char* w2c = (const char*)mlp_w2;
        const char* wcc = (const char*)conv_w;
        size_t off = (size_t)tid * 128;
        asm volatile("prefetch.global.L2 [%0];" :: "l"(w2c + off));
        asm volatile("prefetch.global.L2 [%0];" :: "l"(wcc + off));
    }
    // w1 -> smem (coalesced float4)
    {
        const float4* g4 = reinterpret_cast<const float4*>(mlp_w1);
        #pragma unroll
        for (int v = tid; v < 7168; v += 896) {
            int row = v / 112;           // 112 float4 per 448-float row
            int col = v - row * 112;
            dynw[row * 113 + col] = g4[v];
        }
    }
    // LN params + biases -> smem
    if (tid < 64)   { s_w[tid]       = ln1w[tid]; s_b[tid]       = ln1b[tid]; }
    if (tid < 128)  { s_w[64 + tid]  = ln2w[tid]; s_b[64 + tid]  = ln2b[tid]; }
    if (tid < 256)  { s_w[192 + tid] = ln3w[tid]; s_b[192 + tid] = ln3b[tid]; }
    if (tid < 384)  { s_w[448 + tid] = ln4w[tid]; s_b[448 + tid] = ln4b[tid]; }
    if (tid < 448)  { s_w[832 + tid] = ln5w[tid]; s_b[832 + tid] = ln5b[tid]; }
    if (tid < 64)   s_b1[tid] = mlp_b1[tid];
    if (tid < 448)  s_b2[tid] = mlp_b2[tid];
    if (tid >= 448 && tid < 512) s_bc[tid - 448] = conv_b[tid - 448];

    // ================= WAIT for gap_reduce completion ======================
#if __CUDA_ARCH__ >= 900
    cudaGridDependencySynchronize();
#endif
    __syncthreads();

    // --- Stage g_part into smem, fully coalesced (1408 float4) ---
    {
        const float4* gp4 = reinterpret_cast<const float4*>(g_part);
        float4* sg4 = reinterpret_cast<float4*>(s_g);
        #pragma unroll
        for (int v = tid; v < 1408; v += 896) sg4[v] = gp4[v];
    }
    __syncthreads();

    int b = tid / 448;
    int t = tid - b * 448;
    float* svb = sv[b];

    // --- Assemble raw GAP means from smem ---
    if (t < 64) {                    // x2: rotated index -> conflict-free
        int base = (b * 64 + t) * 32;
        float s = 0.f;
        #pragma unroll
        for (int k = 0; k < 32; k++) s += s_g[base + ((k + t) & 31)];
        svb[t] = s * (1.f / 2097152.f);
    }
    if (t < 128) {
        int base = 4096 + (b * 128 + t) * 4;
        float s = 0.f;
        #pragma unroll
        for (int k = 0; k < 4; k++) s += s_g[base + k];
        svb[64 + t] = s * (1.f / 262144.f);
    }
    if (t < 256) {
        svb[192 + t] = s_g[5120 + b * 256 + t] * (1.f / 32768.f);
    }
    __syncthreads();

    // --- LayerNorm chain ---
    ln_s(svb,        64, t, s_w,       s_b,       sbuf);
    ln_s(svb +  64, 128, t, s_w + 64,  s_b + 64,  sbuf);
    ln_s(svb + 192, 256, t, s_w + 192, s_b + 192, sbuf);
    ln_s(svb +  64, 384, t, s_w + 448, s_b + 448, sbuf);
    ln_s(svb,       448, t, s_w + 832, s_b + 832, sbuf);

    int c = t >> 6;                   // chunk 0..6
    int o = t & 63;                   // output 0..63

    // =======================================================================
    // Stage 1: partial dot over chunk c of row o, weights from smem.
    // =======================================================================
    {
        const float4* wr = dynw + o * 113 + c * 16;
        const float4* xr = reinterpret_cast<const float4*>(svb + c * 64);
        float p = 0.f;
        #pragma unroll
        for (int k = 0; k < 16; k++) {
            float4 wv = wr[k], xv = xr[k];
            p = fmaf(wv.x, xv.x, p); p = fmaf(wv.y, xv.y, p);
            p = fmaf(wv.z, xv.z, p); p = fmaf(wv.w, xv.w, p);
        }
        red[b][t] = p;
    }
    __syncthreads();
    if (tid < 128) {
        int bb = tid >> 6, oo = tid & 63;
        float acc = s_b1[oo];
        #pragma unroll
        for (int cc = 0; cc < 7; cc++) acc += red[bb][cc * 64 + oo];
        h1s[bb][oo] = fmaxf(acc, 0.f);
    }
    __syncthreads();

    // =======================================================================
    // Stage 2: copy w2 (448x64, L2-hot) into smem (17-f4 stride), then
    // thread-per-(b,jj) dot of 64 from smem.
    // =======================================================================
    {
        const float4* g4 = reinterpret_cast<const float4*>(mlp_w2);
        #pragma unroll
        for (int v = tid; v < 7168; v += 896) {
            int row = v >> 4;            // 16 float4 per 64-float row
            int col = v & 15;
            dynw[row * 17 + col] = g4[v];
        }
    }
    __syncthreads();
    {
        const float4* wr = dynw + t * 17;            // row jj = t
        const float4* hr = reinterpret_cast<const float4*>(h1s[b]);
        float acc = s_b2[t];
        #pragma unroll
        for (int k = 0; k < 16; k++) {
            float4 wv = wr[k], hv = hr[k];
            acc = fmaf(wv.x, hv.x, acc); acc = fmaf(wv.y, hv.y, acc);
            acc = fmaf(wv.z, hv.z, acc); acc = fmaf(wv.w, hv.w, acc);
        }
        acc = fmaxf(acc, 0.f);
        __syncthreads();              // all stage-2 smem reads done
        svb[t] = acc;                 // h2 -> sv
    }
    __syncthreads();

    // =======================================================================
    // Stage 3: copy conv_w (L2-hot), chunk-dot, sigmoid finish.
    // =======================================================================
    {
        const float4* g4 = reinterpret_cast<const float4*>(conv_w);
        #pragma unroll
        for (int v = tid; v < 7168; v += 896) {
            int row = v / 112;
            int col = v - row * 112;
            dynw[row * 113 + col] = g4[v];
        }
    }
    __syncthreads();
    {
        const float4* wr = dynw + o * 113 + c * 16;
        const float4* xr = reinterpret_cast<const float4*>(svb + c * 64);
        float p = 0.f;
        #pragma unroll
        for (int k = 0; k < 16; k++) {
            float4 wv = wr[k], xv = xr[k];
            p = fmaf(wv.x, xv.x, p); p = fmaf(wv.y, xv.y, p);
            p = fmaf(wv.z, xv.z, p); p = fmaf(wv.w, xv.w, p);
        }
        red[b][t] = p;
    }
    __syncthreads();
    if (tid < 128) {
        int bb = tid >> 6, oo = tid & 63;
        float acc = s_bc[oo];
        #pragma unroll
        for (int cc = 0; cc < 7; cc++) acc += red[bb][cc * 64 + oo];
        out[bb * 64 + oo] = 1.f / (1.f + expf(-acc));
    }
}

// ---------------------------------------------------------------------------

extern "C" void kernel_launch(void* const* d_in, const int* in_sizes, int n_in,
                              void* d_out, int out_size)
{
    const float* x0 = (const float*)d_in[0];
    const float* x1 = (const float*)d_in[1];
    const float* x2 = (const float*)d_in[2];

    gap_reduce<<<5632, 256>>>(x0, x1, x2);

    const int dyn_bytes = 7616 * 16;   // 121856 B
    static int attr_set = 0;
    if (!attr_set) {
        cudaFuncSetAttribute(epilogue,
                             cudaFuncAttributeMaxDynamicSharedMemorySize,
                             dyn_bytes);
        attr_set = 1;
    }

    cudaLaunchConfig_t cfg = {};
    cfg.gridDim  = dim3(1, 1, 1);
    cfg.blockDim = dim3(896, 1, 1);
    cfg.dynamicSmemBytes = dyn_bytes;
    cudaLaunchAttribute attrs[1];
    attrs[0].id = cudaLaunchAttributeProgrammaticStreamSerialization;
    attrs[0].val.programmaticStreamSerializationAllowed = 1;
    cfg.attrs = attrs;
    cfg.numAttrs = 1;

    cudaLaunchKernelEx(&cfg, epilogue,
        (const float*)d_in[3],  (const float*)d_in[4],
        (const float*)d_in[5],  (const float*)d_in[6],
        (const float*)d_in[7],  (const float*)d_in[8],
        (const float*)d_in[9],  (const float*)d_in[10],
        (const float*)d_in[11], (const float*)d_in[12],
        (const float*)d_in[13], (const float*)d_in[14],
        (const float*)d_in[15], (const float*)d_in[16],
        (const float*)d_in[17], (const float*)d_in[18],
        (float*)d_out);
}